// round 3
// baseline (speedup 1.0000x reference)
#include <cuda_runtime.h>
#include <cuda_bf16.h>
#include <math.h>

// ---------------------------------------------------------------------------
// SingleStreamBlock fp32 baseline
// Shapes: B=1, L=2048, D=3072, H=24, Dh=128, QKV=9216, MLP=12288, CAT=15360
// ---------------------------------------------------------------------------

#define L_   2048
#define D_   3072
#define H_   24
#define DH_  128
#define QKV_ 9216
#define W1N_ 21504      // QKV + 4*D
#define CAT_ 15360      // D + 4*D
#define EPS_ 1e-6f

// Scratch (device globals: allocation-free)
__device__ float g_sv[D_];                       // silu(vec)
__device__ float g_m[3 * D_];                    // shift|scale|gate
__device__ float g_xmod[(size_t)L_ * D_];        // modulated layernorm out
__device__ float g_h[(size_t)L_ * W1N_];         // GEMM1 output (qkv | mlp)
__device__ float g_S[(size_t)H_ * L_ * L_];      // attention logits/probs
__device__ float g_attn[(size_t)L_ * D_];        // attention output
__device__ float g_cat[(size_t)L_ * CAT_];       // [attn | gelu(mlp)]

// ---------------------------------------------------------------------------
// small elementwise / reduction kernels
// ---------------------------------------------------------------------------
__global__ void silu_kernel(const float* __restrict__ v, float* __restrict__ o) {
    int i = blockIdx.x * blockDim.x + threadIdx.x;
    if (i < D_) {
        float x = v[i];
        o[i] = x / (1.0f + expf(-x));
    }
}

// m[j] = b[j] + sum_i sv[i] * w[i*9216 + j]
__global__ void mod_gemv(const float* __restrict__ sv, const float* __restrict__ w,
                         const float* __restrict__ b, float* __restrict__ m) {
    __shared__ float s[D_];
    for (int i = threadIdx.x; i < D_; i += blockDim.x) s[i] = sv[i];
    __syncthreads();
    int j = blockIdx.x * blockDim.x + threadIdx.x;   // 9216 total
    float acc = 0.f;
#pragma unroll 8
    for (int i = 0; i < D_; i++) acc += s[i] * w[(size_t)i * (3 * D_) + j];
    m[j] = acc + b[j];
}

// layernorm + modulate: one block per row
__global__ void ln_mod(const float* __restrict__ x, const float* __restrict__ m,
                       float* __restrict__ xmod) {
    __shared__ float r1[8], r2[8], bc[2];
    int row = blockIdx.x, t = threadIdx.x;
    const float* xr = x + (size_t)row * D_;
    float sum = 0.f, ss = 0.f;
    for (int i = t; i < D_; i += 256) {
        float v = xr[i];
        sum += v; ss += v * v;
    }
#pragma unroll
    for (int o = 16; o > 0; o >>= 1) {
        sum += __shfl_xor_sync(0xffffffffu, sum, o);
        ss  += __shfl_xor_sync(0xffffffffu, ss,  o);
    }
    if ((t & 31) == 0) { r1[t >> 5] = sum; r2[t >> 5] = ss; }
    __syncthreads();
    if (t == 0) {
        float a = 0.f, b = 0.f;
        for (int w = 0; w < 8; w++) { a += r1[w]; b += r2[w]; }
        bc[0] = a; bc[1] = b;
    }
    __syncthreads();
    float mu  = bc[0] * (1.0f / D_);
    float var = bc[1] * (1.0f / D_) - mu * mu;
    float inv = rsqrtf(var + EPS_);
    const float* shift = m;
    const float* scale = m + D_;
    float* orow = xmod + (size_t)row * D_;
    for (int i = t; i < D_; i += 256) {
        float v = (xr[i] - mu) * inv;
        orow[i] = (1.0f + scale[i]) * v + shift[i];
    }
}

// RMSNorm + RoPE for q and k, in place inside g_h. grid (L, H), 64 threads.
__global__ void rmsrope(float* __restrict__ h, const float* __restrict__ pe,
                        const float* __restrict__ qs, const float* __restrict__ ks) {
    __shared__ float red[2];
    int l = blockIdx.x, hh = blockIdx.y, t = threadIdx.x;   // t < 64 (one pair each)
    float* base = h + (size_t)l * W1N_ + hh * DH_;
    const float* p = pe + (size_t)l * 256 + t * 4;          // pe[l, t, j, r]
    for (int s = 0; s < 2; s++) {
        float* ptr = base + s * D_;                          // q then k
        const float* g = s ? ks : qs;
        float a = ptr[2 * t], b = ptr[2 * t + 1];
        float sq = a * a + b * b;
#pragma unroll
        for (int o = 16; o > 0; o >>= 1) sq += __shfl_xor_sync(0xffffffffu, sq, o);
        if ((t & 31) == 0) red[t >> 5] = sq;
        __syncthreads();
        float tot = red[0] + red[1];
        float r = rsqrtf(tot * (1.0f / DH_) + EPS_);
        float na = a * r * g[2 * t];
        float nb = b * r * g[2 * t + 1];
        ptr[2 * t]     = p[0] * na + p[1] * nb;
        ptr[2 * t + 1] = p[2] * na + p[3] * nb;
        __syncthreads();
    }
}

// softmax over rows of length 2048; one block per row (flat over H*L rows)
__global__ void softmax2048(float* __restrict__ S) {
    __shared__ float r[8], bc;
    int t = threadIdx.x;
    float* row = S + (size_t)blockIdx.x * L_;
    float v[8];
    float mx = -1e30f;
#pragma unroll
    for (int i = 0; i < 8; i++) { v[i] = row[t + i * 256]; mx = fmaxf(mx, v[i]); }
#pragma unroll
    for (int o = 16; o > 0; o >>= 1) mx = fmaxf(mx, __shfl_xor_sync(0xffffffffu, mx, o));
    if ((t & 31) == 0) r[t >> 5] = mx;
    __syncthreads();
    if (t == 0) {
        float m2 = r[0];
        for (int w = 1; w < 8; w++) m2 = fmaxf(m2, r[w]);
        bc = m2;
    }
    __syncthreads();
    mx = bc;
    float sum = 0.f;
#pragma unroll
    for (int i = 0; i < 8; i++) { v[i] = expf(v[i] - mx); sum += v[i]; }
#pragma unroll
    for (int o = 16; o > 0; o >>= 1) sum += __shfl_xor_sync(0xffffffffu, sum, o);
    if ((t & 31) == 0) r[t >> 5] = sum;
    __syncthreads();
    if (t == 0) {
        float s2 = 0.f;
        for (int w = 0; w < 8; w++) s2 += r[w];
        bc = s2;
    }
    __syncthreads();
    float inv = 1.0f / bc;
#pragma unroll
    for (int i = 0; i < 8; i++) row[t + i * 256] = v[i] * inv;
}

__device__ __forceinline__ float gelu_tanh(float x) {
    float x3 = x * x * x;
    return 0.5f * x * (1.0f + tanhf(0.7978845608028654f * (x + 0.044715f * x3)));
}

// build cat = [attn | gelu(mlp)]
__global__ void cat_kernel(const float* __restrict__ attn, const float* __restrict__ h,
                           float* __restrict__ cat) {
    size_t idx = (size_t)blockIdx.x * blockDim.x + threadIdx.x;
    if (idx >= (size_t)L_ * CAT_) return;
    int row = (int)(idx / CAT_);
    int c = (int)(idx % CAT_);
    float v;
    if (c < D_) v = attn[(size_t)row * D_ + c];
    else        v = gelu_tanh(h[(size_t)row * W1N_ + QKV_ + (c - D_)]);
    cat[idx] = v;
}

// ---------------------------------------------------------------------------
// Register-tiled fp32 GEMM: C[M,N] = op(A,B), 128x128 tile, BK=8, 256 thr, 8x8/thr
// NT=false: C[i,j] = sum_k A[i,k]*B[k,j]   (A row-major MxK, B row-major KxN)
// NT=true : C[i,j] = sum_k A[i,k]*B[j,k]   (B row-major NxK)
// EPI 0: C = acc + bias[col]
// EPI 1: C = alpha * acc
// EPI 2: C = acc
// EPI 3: C = xres[row*ldc+col] + gate[col] * (acc + bias[col])
// All dims must be multiples of tile sizes (true for this problem).
// ---------------------------------------------------------------------------
template <int EPI, bool NT>
__global__ __launch_bounds__(256) void gemm_kernel(
    const float* __restrict__ A, const float* __restrict__ B, float* __restrict__ C,
    int K, int lda, int ldb, int ldc,
    long long sA, long long sB, long long sC, float alpha,
    const float* __restrict__ bias, const float* __restrict__ xres,
    const float* __restrict__ gate)
{
    __shared__ float As[8][132];
    __shared__ float Bs[8][132];
    A += (long long)blockIdx.z * sA;
    B += (long long)blockIdx.z * sB;
    C += (long long)blockIdx.z * sC;
    const int m0 = blockIdx.y * 128, n0 = blockIdx.x * 128;
    const int tid = threadIdx.x;
    const int tx = tid & 15, ty = tid >> 4;

    float acc[8][8];
#pragma unroll
    for (int i = 0; i < 8; i++)
#pragma unroll
        for (int j = 0; j < 8; j++) acc[i][j] = 0.f;

    for (int k0 = 0; k0 < K; k0 += 8) {
        {   // A tile: 128 rows x 8 k, transpose into As[k][row]
            int r = tid >> 1, kk = (tid & 1) * 4;
            float4 v = *(const float4*)(A + (size_t)(m0 + r) * lda + k0 + kk);
            As[kk + 0][r] = v.x; As[kk + 1][r] = v.y;
            As[kk + 2][r] = v.z; As[kk + 3][r] = v.w;
        }
        if (!NT) {  // B tile: 8 k x 128 cols
            int kk = tid >> 5, c = (tid & 31) * 4;
            float4 v = *(const float4*)(B + (size_t)(k0 + kk) * ldb + n0 + c);
            *(float4*)&Bs[kk][c] = v;
        } else {    // B tile from NxK layout: Bs[k][j] = B[(n0+j)*ldb + k0+k]
            int j = tid >> 1, kk = (tid & 1) * 4;
            float4 v = *(const float4*)(B + (size_t)(n0 + j) * ldb + k0 + kk);
            Bs[kk + 0][j] = v.x; Bs[kk + 1][j] = v.y;
            Bs[kk + 2][j] = v.z; Bs[kk + 3][j] = v.w;
        }
        __syncthreads();
#pragma unroll
        for (int k = 0; k < 8; k++) {
            float a[8], b[8];
            *(float4*)(a)     = *(const float4*)&As[k][ty * 8];
            *(float4*)(a + 4) = *(const float4*)&As[k][ty * 8 + 4];
            *(float4*)(b)     = *(const float4*)&Bs[k][tx * 8];
            *(float4*)(b + 4) = *(const float4*)&Bs[k][tx * 8 + 4];
#pragma unroll
            for (int i = 0; i < 8; i++)
#pragma unroll
                for (int j = 0; j < 8; j++) acc[i][j] += a[i] * b[j];
        }
        __syncthreads();
    }

#pragma unroll
    for (int i = 0; i < 8; i++) {
        size_t row = (size_t)(m0 + ty * 8 + i);
        float* crow = C + row * ldc + n0 + tx * 8;
#pragma unroll
        for (int j = 0; j < 8; j++) {
            int col = n0 + tx * 8 + j;
            float v = acc[i][j];
            if (EPI == 0)      v = v + bias[col];
            else if (EPI == 1) v = v * alpha;
            else if (EPI == 3) v = xres[row * ldc + col] + gate[col] * (v + bias[col]);
            crow[j] = v;
        }
    }
}

// ---------------------------------------------------------------------------
// launcher
// ---------------------------------------------------------------------------
extern "C" void kernel_launch(void* const* d_in, const int* in_sizes, int n_in,
                              void* d_out, int out_size) {
    const float* x      = (const float*)d_in[0];
    const float* vec    = (const float*)d_in[1];
    const float* pe     = (const float*)d_in[2];
    const float* w_mod  = (const float*)d_in[3];
    const float* b_mod  = (const float*)d_in[4];
    const float* w1     = (const float*)d_in[5];
    const float* b1     = (const float*)d_in[6];
    const float* w2     = (const float*)d_in[7];
    const float* b2     = (const float*)d_in[8];
    const float* qscale = (const float*)d_in[9];
    const float* kscale = (const float*)d_in[10];
    float* out = (float*)d_out;

    float *sv, *m, *xmod, *h, *S, *attn, *cat;
    cudaGetSymbolAddress((void**)&sv,   g_sv);
    cudaGetSymbolAddress((void**)&m,    g_m);
    cudaGetSymbolAddress((void**)&xmod, g_xmod);
    cudaGetSymbolAddress((void**)&h,    g_h);
    cudaGetSymbolAddress((void**)&S,    g_S);
    cudaGetSymbolAddress((void**)&attn, g_attn);
    cudaGetSymbolAddress((void**)&cat,  g_cat);

    // 1. silu(vec)
    silu_kernel<<<(D_ + 255) / 256, 256>>>(vec, sv);
    // 2. m = silu(vec) @ w_mod + b_mod
    mod_gemv<<<(3 * D_) / 128, 128>>>(sv, w_mod, b_mod, m);
    // 3. layernorm + modulate
    ln_mod<<<L_, 256>>>(x, m, xmod);
    // 4. h = xmod @ w1 + b1   [2048 x 3072] @ [3072 x 21504]
    gemm_kernel<0, false><<<dim3(W1N_ / 128, L_ / 128, 1), 256>>>(
        xmod, w1, h, D_, D_, W1N_, W1N_, 0, 0, 0, 1.0f, b1, nullptr, nullptr);
    // 5. q/k rmsnorm + rope (in-place in h)
    rmsrope<<<dim3(L_, H_), 64>>>(h, pe, qscale, kscale);
    // 6. S = Q @ K^T * Dh^-0.5   (batched over heads, NT)
    gemm_kernel<1, true><<<dim3(L_ / 128, L_ / 128, H_), 256>>>(
        h, h + D_, S, DH_, W1N_, W1N_, L_,
        (long long)DH_, (long long)DH_, (long long)L_ * L_,
        0.08838834764831845f, nullptr, nullptr, nullptr);
    // 7. softmax rows
    softmax2048<<<H_ * L_, 256>>>(S);
    // 8. attn = P @ V  (batched over heads, NN)
    gemm_kernel<2, false><<<dim3(1, L_ / 128, H_), 256>>>(
        S, h + 2 * D_, attn, L_, L_, W1N_, D_,
        (long long)L_ * L_, (long long)DH_, (long long)DH_,
        1.0f, nullptr, nullptr, nullptr);
    // 9. cat = [attn | gelu(mlp)]
    {
        size_t total = (size_t)L_ * CAT_;
        cat_kernel<<<(unsigned)((total + 255) / 256), 256>>>(attn, h, cat);
    }
    // 10. out = x + gate * (cat @ w2 + b2)
    gemm_kernel<3, false><<<dim3(D_ / 128, L_ / 128, 1), 256>>>(
        cat, w2, out, CAT_, CAT_, D_, D_, 0, 0, 0, 1.0f, b2, x, m + 2 * D_);
}

// round 4
// speedup vs baseline: 2.2750x; 2.2750x over previous
#include <cuda_runtime.h>
#include <cuda_bf16.h>
#include <math.h>
#include <stdint.h>

// ---------------------------------------------------------------------------
// SingleStreamBlock — tf32 tensor-core GEMMs
// Shapes: B=1, L=2048, D=3072, H=24, Dh=128, QKV=9216, MLP=12288, CAT=15360
// ---------------------------------------------------------------------------

#define L_   2048
#define D_   3072
#define H_   24
#define DH_  128
#define QKV_ 9216
#define W1N_ 21504      // QKV + 4*D
#define CAT_ 15360      // D + 4*D
#define EPS_ 1e-6f

// Scratch (device globals: allocation-free)
__device__ float g_sv[D_];
__device__ float g_m[3 * D_];
__device__ float g_xmod[(size_t)L_ * D_];
__device__ float g_h[(size_t)L_ * W1N_];
__device__ float g_S[(size_t)H_ * L_ * L_];
__device__ float g_attn[(size_t)L_ * D_];
__device__ float g_cat[(size_t)L_ * CAT_];

// ---------------------------------------------------------------------------
// small elementwise / reduction kernels (unchanged from fp32 baseline)
// ---------------------------------------------------------------------------
__global__ void silu_kernel(const float* __restrict__ v, float* __restrict__ o) {
    int i = blockIdx.x * blockDim.x + threadIdx.x;
    if (i < D_) {
        float x = v[i];
        o[i] = x / (1.0f + expf(-x));
    }
}

__global__ void mod_gemv(const float* __restrict__ sv, const float* __restrict__ w,
                         const float* __restrict__ b, float* __restrict__ m) {
    __shared__ float s[D_];
    for (int i = threadIdx.x; i < D_; i += blockDim.x) s[i] = sv[i];
    __syncthreads();
    int j = blockIdx.x * blockDim.x + threadIdx.x;
    float acc = 0.f;
#pragma unroll 8
    for (int i = 0; i < D_; i++) acc += s[i] * w[(size_t)i * (3 * D_) + j];
    m[j] = acc + b[j];
}

__global__ void ln_mod(const float* __restrict__ x, const float* __restrict__ m,
                       float* __restrict__ xmod) {
    __shared__ float r1[8], r2[8], bc[2];
    int row = blockIdx.x, t = threadIdx.x;
    const float* xr = x + (size_t)row * D_;
    float sum = 0.f, ss = 0.f;
    for (int i = t; i < D_; i += 256) {
        float v = xr[i];
        sum += v; ss += v * v;
    }
#pragma unroll
    for (int o = 16; o > 0; o >>= 1) {
        sum += __shfl_xor_sync(0xffffffffu, sum, o);
        ss  += __shfl_xor_sync(0xffffffffu, ss,  o);
    }
    if ((t & 31) == 0) { r1[t >> 5] = sum; r2[t >> 5] = ss; }
    __syncthreads();
    if (t == 0) {
        float a = 0.f, b = 0.f;
        for (int w = 0; w < 8; w++) { a += r1[w]; b += r2[w]; }
        bc[0] = a; bc[1] = b;
    }
    __syncthreads();
    float mu  = bc[0] * (1.0f / D_);
    float var = bc[1] * (1.0f / D_) - mu * mu;
    float inv = rsqrtf(var + EPS_);
    const float* shift = m;
    const float* scale = m + D_;
    float* orow = xmod + (size_t)row * D_;
    for (int i = t; i < D_; i += 256) {
        float v = (xr[i] - mu) * inv;
        orow[i] = (1.0f + scale[i]) * v + shift[i];
    }
}

__global__ void rmsrope(float* __restrict__ h, const float* __restrict__ pe,
                        const float* __restrict__ qs, const float* __restrict__ ks) {
    __shared__ float red[2];
    int l = blockIdx.x, hh = blockIdx.y, t = threadIdx.x;
    float* base = h + (size_t)l * W1N_ + hh * DH_;
    const float* p = pe + (size_t)l * 256 + t * 4;
    for (int s = 0; s < 2; s++) {
        float* ptr = base + s * D_;
        const float* g = s ? ks : qs;
        float a = ptr[2 * t], b = ptr[2 * t + 1];
        float sq = a * a + b * b;
#pragma unroll
        for (int o = 16; o > 0; o >>= 1) sq += __shfl_xor_sync(0xffffffffu, sq, o);
        if ((t & 31) == 0) red[t >> 5] = sq;
        __syncthreads();
        float tot = red[0] + red[1];
        float r = rsqrtf(tot * (1.0f / DH_) + EPS_);
        float na = a * r * g[2 * t];
        float nb = b * r * g[2 * t + 1];
        ptr[2 * t]     = p[0] * na + p[1] * nb;
        ptr[2 * t + 1] = p[2] * na + p[3] * nb;
        __syncthreads();
    }
}

__global__ void softmax2048(float* __restrict__ S) {
    __shared__ float r[8], bc;
    int t = threadIdx.x;
    float* row = S + (size_t)blockIdx.x * L_;
    float v[8];
    float mx = -1e30f;
#pragma unroll
    for (int i = 0; i < 8; i++) { v[i] = row[t + i * 256]; mx = fmaxf(mx, v[i]); }
#pragma unroll
    for (int o = 16; o > 0; o >>= 1) mx = fmaxf(mx, __shfl_xor_sync(0xffffffffu, mx, o));
    if ((t & 31) == 0) r[t >> 5] = mx;
    __syncthreads();
    if (t == 0) {
        float m2 = r[0];
        for (int w = 1; w < 8; w++) m2 = fmaxf(m2, r[w]);
        bc = m2;
    }
    __syncthreads();
    mx = bc;
    float sum = 0.f;
#pragma unroll
    for (int i = 0; i < 8; i++) { v[i] = expf(v[i] - mx); sum += v[i]; }
#pragma unroll
    for (int o = 16; o > 0; o >>= 1) sum += __shfl_xor_sync(0xffffffffu, sum, o);
    if ((t & 31) == 0) r[t >> 5] = sum;
    __syncthreads();
    if (t == 0) {
        float s2 = 0.f;
        for (int w = 0; w < 8; w++) s2 += r[w];
        bc = s2;
    }
    __syncthreads();
    float inv = 1.0f / bc;
#pragma unroll
    for (int i = 0; i < 8; i++) row[t + i * 256] = v[i] * inv;
}

__device__ __forceinline__ float gelu_tanh(float x) {
    float x3 = x * x * x;
    return 0.5f * x * (1.0f + tanhf(0.7978845608028654f * (x + 0.044715f * x3)));
}

__global__ void cat_kernel(const float* __restrict__ attn, const float* __restrict__ h,
                           float* __restrict__ cat) {
    size_t idx = (size_t)blockIdx.x * blockDim.x + threadIdx.x;
    if (idx >= (size_t)L_ * CAT_) return;
    int row = (int)(idx / CAT_);
    int c = (int)(idx % CAT_);
    float v;
    if (c < D_) v = attn[(size_t)row * D_ + c];
    else        v = gelu_tanh(h[(size_t)row * W1N_ + QKV_ + (c - D_)]);
    cat[idx] = v;
}

// ---------------------------------------------------------------------------
// tf32 tensor-core GEMM
// Tile 128x128, BK=16, 256 threads = 8 warps (2 m x 4 n), warp tile 64x32.
// mma.sync.aligned.m16n8k8.row.col.f32.tf32.tf32.f32
// Smem K-major with stride 136 words -> conflict-free fragment loads:
//   bank(a0) = (q*8 + g) % 32 covers all 32 banks exactly once.
// NT=false: C = A[M,K] x B[K,N] (both row-major)
// NT=true : C = A[M,K] x B[N,K] (B row-major NxK)
// EPI 0: +bias[col] | 1: *alpha | 2: none | 3: xres + gate[col]*(acc+bias[col])
// ---------------------------------------------------------------------------
#define SMS 136   // smem row stride in words

__device__ __forceinline__ uint32_t f2tf32(float x) {
    uint32_t r;
    asm("cvt.rna.tf32.f32 %0, %1;" : "=r"(r) : "f"(x));
    return r;
}

__device__ __forceinline__ void mma_tf32(float c[4], const uint32_t a[4],
                                         const uint32_t b[2]) {
    asm volatile(
        "mma.sync.aligned.m16n8k8.row.col.f32.tf32.tf32.f32 "
        "{%0,%1,%2,%3}, {%4,%5,%6,%7}, {%8,%9}, {%0,%1,%2,%3};"
        : "+f"(c[0]), "+f"(c[1]), "+f"(c[2]), "+f"(c[3])
        : "r"(a[0]), "r"(a[1]), "r"(a[2]), "r"(a[3]), "r"(b[0]), "r"(b[1]));
}

template <int EPI, bool NT>
__global__ __launch_bounds__(256) void gemm_tf32(
    const float* __restrict__ A, const float* __restrict__ B, float* __restrict__ C,
    int K, int lda, int ldb, int ldc,
    long long sA, long long sB, long long sC, float alpha,
    const float* __restrict__ bias, const float* __restrict__ xres,
    const float* __restrict__ gate)
{
    __shared__ uint32_t As[16 * SMS];
    __shared__ uint32_t Bs[16 * SMS];
    A += (long long)blockIdx.z * sA;
    B += (long long)blockIdx.z * sB;
    C += (long long)blockIdx.z * sC;
    const int m0 = blockIdx.y * 128, n0 = blockIdx.x * 128;
    const int tid = threadIdx.x;
    const int warp = tid >> 5, lane = tid & 31;
    const int wm = (warp & 1) * 64;      // warp m-offset within tile
    const int wn = (warp >> 1) * 32;     // warp n-offset within tile
    const int g = lane >> 2, q = lane & 3;

    float acc[4][4][4];
#pragma unroll
    for (int mi = 0; mi < 4; mi++)
#pragma unroll
        for (int nj = 0; nj < 4; nj++)
#pragma unroll
            for (int e = 0; e < 4; e++) acc[mi][nj][e] = 0.f;

    const int ar = tid >> 1;               // 0..127 (row for transposed loads)
    const int ak = (tid & 1) * 8;          // k sub-offset
    const int bk = tid >> 4;               // 0..15 (NN B row)
    const int bc = (tid & 15) * 8;         // NN B col

    for (int k0 = 0; k0 < K; k0 += 16) {
        {   // A: [128 rows x 16 k] -> As[k][m] (transposed), tf32-converted
            const float* ap = A + (size_t)(m0 + ar) * lda + k0 + ak;
            float4 v0 = *(const float4*)(ap);
            float4 v1 = *(const float4*)(ap + 4);
            As[(ak + 0) * SMS + ar] = f2tf32(v0.x);
            As[(ak + 1) * SMS + ar] = f2tf32(v0.y);
            As[(ak + 2) * SMS + ar] = f2tf32(v0.z);
            As[(ak + 3) * SMS + ar] = f2tf32(v0.w);
            As[(ak + 4) * SMS + ar] = f2tf32(v1.x);
            As[(ak + 5) * SMS + ar] = f2tf32(v1.y);
            As[(ak + 6) * SMS + ar] = f2tf32(v1.z);
            As[(ak + 7) * SMS + ar] = f2tf32(v1.w);
        }
        if (!NT) {  // B KxN row-major -> Bs[k][n] direct (vector stores)
            const float* bp = B + (size_t)(k0 + bk) * ldb + n0 + bc;
            float4 v0 = *(const float4*)(bp);
            float4 v1 = *(const float4*)(bp + 4);
            uint4 u0 = make_uint4(f2tf32(v0.x), f2tf32(v0.y), f2tf32(v0.z), f2tf32(v0.w));
            uint4 u1 = make_uint4(f2tf32(v1.x), f2tf32(v1.y), f2tf32(v1.z), f2tf32(v1.w));
            *(uint4*)&Bs[bk * SMS + bc]     = u0;
            *(uint4*)&Bs[bk * SMS + bc + 4] = u1;
        } else {    // B NxK row-major -> Bs[k][n] transposed
            const float* bp = B + (size_t)(n0 + ar) * ldb + k0 + ak;
            float4 v0 = *(const float4*)(bp);
            float4 v1 = *(const float4*)(bp + 4);
            Bs[(ak + 0) * SMS + ar] = f2tf32(v0.x);
            Bs[(ak + 1) * SMS + ar] = f2tf32(v0.y);
            Bs[(ak + 2) * SMS + ar] = f2tf32(v0.z);
            Bs[(ak + 3) * SMS + ar] = f2tf32(v0.w);
            Bs[(ak + 4) * SMS + ar] = f2tf32(v1.x);
            Bs[(ak + 5) * SMS + ar] = f2tf32(v1.y);
            Bs[(ak + 6) * SMS + ar] = f2tf32(v1.z);
            Bs[(ak + 7) * SMS + ar] = f2tf32(v1.w);
        }
        __syncthreads();

#pragma unroll
        for (int ksp = 0; ksp < 2; ksp++) {
            const int kq0 = (ksp * 8 + q) * SMS;
            const int kq4 = (ksp * 8 + q + 4) * SMS;
            uint32_t af[4][4];
#pragma unroll
            for (int mi = 0; mi < 4; mi++) {
                int m = wm + mi * 16 + g;
                af[mi][0] = As[kq0 + m];
                af[mi][1] = As[kq0 + m + 8];
                af[mi][2] = As[kq4 + m];
                af[mi][3] = As[kq4 + m + 8];
            }
            uint32_t bf[4][2];
#pragma unroll
            for (int nj = 0; nj < 4; nj++) {
                int n = wn + nj * 8 + g;
                bf[nj][0] = Bs[kq0 + n];
                bf[nj][1] = Bs[kq4 + n];
            }
#pragma unroll
            for (int mi = 0; mi < 4; mi++)
#pragma unroll
                for (int nj = 0; nj < 4; nj++)
                    mma_tf32(acc[mi][nj], af[mi], bf[nj]);
        }
        __syncthreads();
    }

    // epilogue: c0,c1 at (row g, col 2q..2q+1); c2,c3 at (row g+8)
#pragma unroll
    for (int mi = 0; mi < 4; mi++) {
#pragma unroll
        for (int hh = 0; hh < 2; hh++) {
            size_t row = (size_t)(m0 + wm + mi * 16 + g + hh * 8);
#pragma unroll
            for (int nj = 0; nj < 4; nj++) {
                int col = n0 + wn + nj * 8 + 2 * q;
                float v0 = acc[mi][nj][hh * 2 + 0];
                float v1 = acc[mi][nj][hh * 2 + 1];
                if (EPI == 0) {
                    v0 += bias[col]; v1 += bias[col + 1];
                } else if (EPI == 1) {
                    v0 *= alpha; v1 *= alpha;
                } else if (EPI == 3) {
                    v0 = xres[row * ldc + col]     + gate[col]     * (v0 + bias[col]);
                    v1 = xres[row * ldc + col + 1] + gate[col + 1] * (v1 + bias[col + 1]);
                }
                *(float2*)(C + row * ldc + col) = make_float2(v0, v1);
            }
        }
    }
}

// ---------------------------------------------------------------------------
// launcher
// ---------------------------------------------------------------------------
extern "C" void kernel_launch(void* const* d_in, const int* in_sizes, int n_in,
                              void* d_out, int out_size) {
    const float* x      = (const float*)d_in[0];
    const float* vec    = (const float*)d_in[1];
    const float* pe     = (const float*)d_in[2];
    const float* w_mod  = (const float*)d_in[3];
    const float* b_mod  = (const float*)d_in[4];
    const float* w1     = (const float*)d_in[5];
    const float* b1     = (const float*)d_in[6];
    const float* w2     = (const float*)d_in[7];
    const float* b2     = (const float*)d_in[8];
    const float* qscale = (const float*)d_in[9];
    const float* kscale = (const float*)d_in[10];
    float* out = (float*)d_out;

    float *sv, *m, *xmod, *h, *S, *attn, *cat;
    cudaGetSymbolAddress((void**)&sv,   g_sv);
    cudaGetSymbolAddress((void**)&m,    g_m);
    cudaGetSymbolAddress((void**)&xmod, g_xmod);
    cudaGetSymbolAddress((void**)&h,    g_h);
    cudaGetSymbolAddress((void**)&S,    g_S);
    cudaGetSymbolAddress((void**)&attn, g_attn);
    cudaGetSymbolAddress((void**)&cat,  g_cat);

    // 1. silu(vec)
    silu_kernel<<<(D_ + 255) / 256, 256>>>(vec, sv);
    // 2. m = silu(vec) @ w_mod + b_mod
    mod_gemv<<<(3 * D_) / 128, 128>>>(sv, w_mod, b_mod, m);
    // 3. layernorm + modulate
    ln_mod<<<L_, 256>>>(x, m, xmod);
    // 4. h = xmod @ w1 + b1   [2048 x 3072] @ [3072 x 21504]
    gemm_tf32<0, false><<<dim3(W1N_ / 128, L_ / 128, 1), 256>>>(
        xmod, w1, h, D_, D_, W1N_, W1N_, 0, 0, 0, 1.0f, b1, nullptr, nullptr);
    // 5. q/k rmsnorm + rope (in-place in h)
    rmsrope<<<dim3(L_, H_), 64>>>(h, pe, qscale, kscale);
    // 6. S = Q @ K^T * Dh^-0.5   (batched over heads, NT)
    gemm_tf32<1, true><<<dim3(L_ / 128, L_ / 128, H_), 256>>>(
        h, h + D_, S, DH_, W1N_, W1N_, L_,
        (long long)DH_, (long long)DH_, (long long)L_ * L_,
        0.08838834764831845f, nullptr, nullptr, nullptr);
    // 7. softmax rows
    softmax2048<<<H_ * L_, 256>>>(S);
    // 8. attn = P @ V  (batched over heads, NN)
    gemm_tf32<2, false><<<dim3(1, L_ / 128, H_), 256>>>(
        S, h + 2 * D_, attn, L_, L_, W1N_, D_,
        (long long)L_ * L_, (long long)DH_, (long long)DH_,
        1.0f, nullptr, nullptr, nullptr);
    // 9. cat = [attn | gelu(mlp)]
    {
        size_t total = (size_t)L_ * CAT_;
        cat_kernel<<<(unsigned)((total + 255) / 256), 256>>>(attn, h, cat);
    }
    // 10. out = x + gate * (cat @ w2 + b2)
    gemm_tf32<3, false><<<dim3(D_ / 128, L_ / 128, 1), 256>>>(
        cat, w2, out, CAT_, CAT_, D_, D_, 0, 0, 0, 1.0f, b2, x, m + 2 * D_);
}

// round 5
// speedup vs baseline: 2.7681x; 1.2168x over previous
#include <cuda_runtime.h>
#include <cuda_bf16.h>
#include <math.h>
#include <stdint.h>

// ---------------------------------------------------------------------------
// SingleStreamBlock — tf32 tensor-core GEMMs, double-buffered
// Shapes: B=1, L=2048, D=3072, H=24, Dh=128, QKV=9216, MLP=12288, CAT=15360
// ---------------------------------------------------------------------------

#define L_   2048
#define D_   3072
#define H_   24
#define DH_  128
#define QKV_ 9216
#define W1N_ 21504      // QKV + 4*D
#define CAT_ 15360      // D + 4*D
#define EPS_ 1e-6f

// Scratch (device globals: allocation-free)
__device__ float g_sv[D_];
__device__ float g_m[3 * D_];
__device__ float g_xmod[(size_t)L_ * D_];
__device__ float g_h[(size_t)L_ * W1N_];
__device__ float g_S[(size_t)H_ * L_ * L_];
__device__ float g_attn[(size_t)L_ * D_];
__device__ float g_cat[(size_t)L_ * CAT_];

// ---------------------------------------------------------------------------
// small elementwise / reduction kernels
// ---------------------------------------------------------------------------

// sv = silu(vec) for i<D ; m = b_mod (init for atomic accumulation), 9216 thr
__global__ void silu_init(const float* __restrict__ v, const float* __restrict__ b,
                          float* __restrict__ sv, float* __restrict__ m) {
    int i = blockIdx.x * blockDim.x + threadIdx.x;
    if (i < D_) {
        float x = v[i];
        sv[i] = x / (1.0f + expf(-x));
    }
    if (i < 3 * D_) m[i] = b[i];
}

// partial dot over i-chunk of 384, atomicAdd into m. grid (72, 8), 128 thr
__global__ void mod_gemv(const float* __restrict__ sv, const float* __restrict__ w,
                         float* __restrict__ m) {
    __shared__ float s[384];
    int i0 = blockIdx.y * 384;
    for (int i = threadIdx.x; i < 384; i += 128) s[i] = sv[i0 + i];
    __syncthreads();
    int j = blockIdx.x * 128 + threadIdx.x;
    float acc = 0.f;
#pragma unroll 8
    for (int i = 0; i < 384; i++) acc += s[i] * w[(size_t)(i0 + i) * (3 * D_) + j];
    atomicAdd(&m[j], acc);
}

__global__ void ln_mod(const float* __restrict__ x, const float* __restrict__ m,
                       float* __restrict__ xmod) {
    __shared__ float r1[8], r2[8], bc[2];
    int row = blockIdx.x, t = threadIdx.x;
    const float* xr = x + (size_t)row * D_;
    float sum = 0.f, ss = 0.f;
    for (int i = t; i < D_; i += 256) {
        float v = xr[i];
        sum += v; ss += v * v;
    }
#pragma unroll
    for (int o = 16; o > 0; o >>= 1) {
        sum += __shfl_xor_sync(0xffffffffu, sum, o);
        ss  += __shfl_xor_sync(0xffffffffu, ss,  o);
    }
    if ((t & 31) == 0) { r1[t >> 5] = sum; r2[t >> 5] = ss; }
    __syncthreads();
    if (t == 0) {
        float a = 0.f, b = 0.f;
        for (int w = 0; w < 8; w++) { a += r1[w]; b += r2[w]; }
        bc[0] = a; bc[1] = b;
    }
    __syncthreads();
    float mu  = bc[0] * (1.0f / D_);
    float var = bc[1] * (1.0f / D_) - mu * mu;
    float inv = rsqrtf(var + EPS_);
    const float* shift = m;
    const float* scale = m + D_;
    float* orow = xmod + (size_t)row * D_;
    for (int i = t; i < D_; i += 256) {
        float v = (xr[i] - mu) * inv;
        orow[i] = (1.0f + scale[i]) * v + shift[i];
    }
}

__global__ void rmsrope(float* __restrict__ h, const float* __restrict__ pe,
                        const float* __restrict__ qs, const float* __restrict__ ks) {
    __shared__ float red[2];
    int l = blockIdx.x, hh = blockIdx.y, t = threadIdx.x;
    float* base = h + (size_t)l * W1N_ + hh * DH_;
    const float* p = pe + (size_t)l * 256 + t * 4;
    for (int s = 0; s < 2; s++) {
        float* ptr = base + s * D_;
        const float* g = s ? ks : qs;
        float a = ptr[2 * t], b = ptr[2 * t + 1];
        float sq = a * a + b * b;
#pragma unroll
        for (int o = 16; o > 0; o >>= 1) sq += __shfl_xor_sync(0xffffffffu, sq, o);
        if ((t & 31) == 0) red[t >> 5] = sq;
        __syncthreads();
        float tot = red[0] + red[1];
        float r = rsqrtf(tot * (1.0f / DH_) + EPS_);
        float na = a * r * g[2 * t];
        float nb = b * r * g[2 * t + 1];
        ptr[2 * t]     = p[0] * na + p[1] * nb;
        ptr[2 * t + 1] = p[2] * na + p[3] * nb;
        __syncthreads();
    }
}

__global__ void softmax2048(float* __restrict__ S) {
    __shared__ float r[8], bc;
    int t = threadIdx.x;
    float* row = S + (size_t)blockIdx.x * L_;
    float v[8];
    float mx = -1e30f;
#pragma unroll
    for (int i = 0; i < 8; i++) { v[i] = row[t + i * 256]; mx = fmaxf(mx, v[i]); }
#pragma unroll
    for (int o = 16; o > 0; o >>= 1) mx = fmaxf(mx, __shfl_xor_sync(0xffffffffu, mx, o));
    if ((t & 31) == 0) r[t >> 5] = mx;
    __syncthreads();
    if (t == 0) {
        float m2 = r[0];
        for (int w = 1; w < 8; w++) m2 = fmaxf(m2, r[w]);
        bc = m2;
    }
    __syncthreads();
    mx = bc;
    float sum = 0.f;
#pragma unroll
    for (int i = 0; i < 8; i++) { v[i] = expf(v[i] - mx); sum += v[i]; }
#pragma unroll
    for (int o = 16; o > 0; o >>= 1) sum += __shfl_xor_sync(0xffffffffu, sum, o);
    if ((t & 31) == 0) r[t >> 5] = sum;
    __syncthreads();
    if (t == 0) {
        float s2 = 0.f;
        for (int w = 0; w < 8; w++) s2 += r[w];
        bc = s2;
    }
    __syncthreads();
    float inv = 1.0f / bc;
#pragma unroll
    for (int i = 0; i < 8; i++) row[t + i * 256] = v[i] * inv;
}

__device__ __forceinline__ float gelu_tanh(float x) {
    float x3 = x * x * x;
    return 0.5f * x * (1.0f + tanhf(0.7978845608028654f * (x + 0.044715f * x3)));
}

__global__ void cat_kernel(const float* __restrict__ attn, const float* __restrict__ h,
                           float* __restrict__ cat) {
    size_t idx = (size_t)blockIdx.x * blockDim.x + threadIdx.x;
    if (idx >= (size_t)L_ * CAT_) return;
    int row = (int)(idx / CAT_);
    int c = (int)(idx % CAT_);
    float v;
    if (c < D_) v = attn[(size_t)row * D_ + c];
    else        v = gelu_tanh(h[(size_t)row * W1N_ + QKV_ + (c - D_)]);
    cat[idx] = v;
}

// ---------------------------------------------------------------------------
// tf32 tensor-core GEMM, double-buffered.
// Tile 128x128, BK=16, 256 threads = 8 warps (2m x 4n), warp tile 64x32.
// Smem K-major, stride 136 words -> conflict-free fragment loads.
// Pipeline: issue next tile's LDG into regs, MMA current stage, store regs
// to other stage, one __syncthreads per tile.
// ---------------------------------------------------------------------------
#define SMS 136

__device__ __forceinline__ uint32_t f2tf32(float x) {
    uint32_t r;
    asm("cvt.rna.tf32.f32 %0, %1;" : "=r"(r) : "f"(x));
    return r;
}

__device__ __forceinline__ void mma_tf32(float c[4], const uint32_t a[4],
                                         const uint32_t b[2]) {
    asm volatile(
        "mma.sync.aligned.m16n8k8.row.col.f32.tf32.tf32.f32 "
        "{%0,%1,%2,%3}, {%4,%5,%6,%7}, {%8,%9}, {%0,%1,%2,%3};"
        : "+f"(c[0]), "+f"(c[1]), "+f"(c[2]), "+f"(c[3])
        : "r"(a[0]), "r"(a[1]), "r"(a[2]), "r"(a[3]), "r"(b[0]), "r"(b[1]));
}

template <int EPI, bool NT>
__global__ __launch_bounds__(256) void gemm_tf32(
    const float* __restrict__ A, const float* __restrict__ B, float* __restrict__ C,
    int K, int lda, int ldb, int ldc,
    long long sA, long long sB, long long sC, float alpha,
    const float* __restrict__ bias, const float* __restrict__ xres,
    const float* __restrict__ gate)
{
    __shared__ uint32_t As[2][16 * SMS];
    __shared__ uint32_t Bs[2][16 * SMS];
    A += (long long)blockIdx.z * sA;
    B += (long long)blockIdx.z * sB;
    C += (long long)blockIdx.z * sC;
    const int m0 = blockIdx.y * 128, n0 = blockIdx.x * 128;
    const int tid = threadIdx.x;
    const int warp = tid >> 5, lane = tid & 31;
    const int wm = (warp & 1) * 64;
    const int wn = (warp >> 1) * 32;
    const int g = lane >> 2, q = lane & 3;

    const int ar = tid >> 1;               // 0..127
    const int ak = (tid & 1) * 8;
    const int bk = tid >> 4;               // 0..15
    const int bc = (tid & 15) * 8;

    float acc[4][4][4];
#pragma unroll
    for (int mi = 0; mi < 4; mi++)
#pragma unroll
        for (int nj = 0; nj < 4; nj++)
#pragma unroll
            for (int e = 0; e < 4; e++) acc[mi][nj][e] = 0.f;

    float4 ra0, ra1, rb0, rb1;

    auto ld_tile = [&](int k0) {
        const float* ap = A + (size_t)(m0 + ar) * lda + k0 + ak;
        ra0 = *(const float4*)(ap);
        ra1 = *(const float4*)(ap + 4);
        if (!NT) {
            const float* bp = B + (size_t)(k0 + bk) * ldb + n0 + bc;
            rb0 = *(const float4*)(bp);
            rb1 = *(const float4*)(bp + 4);
        } else {
            const float* bp = B + (size_t)(n0 + ar) * ldb + k0 + ak;
            rb0 = *(const float4*)(bp);
            rb1 = *(const float4*)(bp + 4);
        }
    };

    auto st_tile = [&](int st) {
        uint32_t* Asb = As[st];
        Asb[(ak + 0) * SMS + ar] = f2tf32(ra0.x);
        Asb[(ak + 1) * SMS + ar] = f2tf32(ra0.y);
        Asb[(ak + 2) * SMS + ar] = f2tf32(ra0.z);
        Asb[(ak + 3) * SMS + ar] = f2tf32(ra0.w);
        Asb[(ak + 4) * SMS + ar] = f2tf32(ra1.x);
        Asb[(ak + 5) * SMS + ar] = f2tf32(ra1.y);
        Asb[(ak + 6) * SMS + ar] = f2tf32(ra1.z);
        Asb[(ak + 7) * SMS + ar] = f2tf32(ra1.w);
        uint32_t* Bsb = Bs[st];
        if (!NT) {
            uint4 u0 = make_uint4(f2tf32(rb0.x), f2tf32(rb0.y), f2tf32(rb0.z), f2tf32(rb0.w));
            uint4 u1 = make_uint4(f2tf32(rb1.x), f2tf32(rb1.y), f2tf32(rb1.z), f2tf32(rb1.w));
            *(uint4*)&Bsb[bk * SMS + bc]     = u0;
            *(uint4*)&Bsb[bk * SMS + bc + 4] = u1;
        } else {
            Bsb[(ak + 0) * SMS + ar] = f2tf32(rb0.x);
            Bsb[(ak + 1) * SMS + ar] = f2tf32(rb0.y);
            Bsb[(ak + 2) * SMS + ar] = f2tf32(rb0.z);
            Bsb[(ak + 3) * SMS + ar] = f2tf32(rb0.w);
            Bsb[(ak + 4) * SMS + ar] = f2tf32(rb1.x);
            Bsb[(ak + 5) * SMS + ar] = f2tf32(rb1.y);
            Bsb[(ak + 6) * SMS + ar] = f2tf32(rb1.z);
            Bsb[(ak + 7) * SMS + ar] = f2tf32(rb1.w);
        }
    };

    // prologue: tile 0 into stage 0
    ld_tile(0);
    st_tile(0);
    __syncthreads();

    const int nk = K >> 4;
    for (int it = 0; it < nk; it++) {
        const int st = it & 1;
        if (it + 1 < nk) ld_tile((it + 1) << 4);   // LDGs in flight during MMA

        const uint32_t* Asb = As[st];
        const uint32_t* Bsb = Bs[st];
#pragma unroll
        for (int ksp = 0; ksp < 2; ksp++) {
            const int kq0 = (ksp * 8 + q) * SMS;
            const int kq4 = (ksp * 8 + q + 4) * SMS;
            uint32_t af[4][4];
#pragma unroll
            for (int mi = 0; mi < 4; mi++) {
                int m = wm + mi * 16 + g;
                af[mi][0] = Asb[kq0 + m];
                af[mi][1] = Asb[kq0 + m + 8];
                af[mi][2] = Asb[kq4 + m];
                af[mi][3] = Asb[kq4 + m + 8];
            }
            uint32_t bf[4][2];
#pragma unroll
            for (int nj = 0; nj < 4; nj++) {
                int n = wn + nj * 8 + g;
                bf[nj][0] = Bsb[kq0 + n];
                bf[nj][1] = Bsb[kq4 + n];
            }
#pragma unroll
            for (int mi = 0; mi < 4; mi++)
#pragma unroll
                for (int nj = 0; nj < 4; nj++)
                    mma_tf32(acc[mi][nj], af[mi], bf[nj]);
        }

        if (it + 1 < nk) st_tile(st ^ 1);
        __syncthreads();
    }

    // epilogue
#pragma unroll
    for (int mi = 0; mi < 4; mi++) {
#pragma unroll
        for (int hh = 0; hh < 2; hh++) {
            size_t row = (size_t)(m0 + wm + mi * 16 + g + hh * 8);
#pragma unroll
            for (int nj = 0; nj < 4; nj++) {
                int col = n0 + wn + nj * 8 + 2 * q;
                float v0 = acc[mi][nj][hh * 2 + 0];
                float v1 = acc[mi][nj][hh * 2 + 1];
                if (EPI == 0) {
                    v0 += bias[col]; v1 += bias[col + 1];
                } else if (EPI == 1) {
                    v0 *= alpha; v1 *= alpha;
                } else if (EPI == 3) {
                    v0 = xres[row * ldc + col]     + gate[col]     * (v0 + bias[col]);
                    v1 = xres[row * ldc + col + 1] + gate[col + 1] * (v1 + bias[col + 1]);
                }
                *(float2*)(C + row * ldc + col) = make_float2(v0, v1);
            }
        }
    }
}

// ---------------------------------------------------------------------------
// launcher
// ---------------------------------------------------------------------------
extern "C" void kernel_launch(void* const* d_in, const int* in_sizes, int n_in,
                              void* d_out, int out_size) {
    const float* x      = (const float*)d_in[0];
    const float* vec    = (const float*)d_in[1];
    const float* pe     = (const float*)d_in[2];
    const float* w_mod  = (const float*)d_in[3];
    const float* b_mod  = (const float*)d_in[4];
    const float* w1     = (const float*)d_in[5];
    const float* b1     = (const float*)d_in[6];
    const float* w2     = (const float*)d_in[7];
    const float* b2     = (const float*)d_in[8];
    const float* qscale = (const float*)d_in[9];
    const float* kscale = (const float*)d_in[10];
    float* out = (float*)d_out;

    float *sv, *m, *xmod, *h, *S, *attn, *cat;
    cudaGetSymbolAddress((void**)&sv,   g_sv);
    cudaGetSymbolAddress((void**)&m,    g_m);
    cudaGetSymbolAddress((void**)&xmod, g_xmod);
    cudaGetSymbolAddress((void**)&h,    g_h);
    cudaGetSymbolAddress((void**)&S,    g_S);
    cudaGetSymbolAddress((void**)&attn, g_attn);
    cudaGetSymbolAddress((void**)&cat,  g_cat);

    // 1. sv = silu(vec); m = b_mod
    silu_init<<<(3 * D_) / 256, 256>>>(vec, b_mod, sv, m);
    // 2. m += silu(vec) @ w_mod   (K split 8 ways, atomic accumulate)
    mod_gemv<<<dim3(72, 8), 128>>>(sv, w_mod, m);
    // 3. layernorm + modulate
    ln_mod<<<L_, 256>>>(x, m, xmod);
    // 4. h = xmod @ w1 + b1
    gemm_tf32<0, false><<<dim3(W1N_ / 128, L_ / 128, 1), 256>>>(
        xmod, w1, h, D_, D_, W1N_, W1N_, 0, 0, 0, 1.0f, b1, nullptr, nullptr);
    // 5. q/k rmsnorm + rope (in-place in h)
    rmsrope<<<dim3(L_, H_), 64>>>(h, pe, qscale, kscale);
    // 6. S = Q @ K^T * Dh^-0.5
    gemm_tf32<1, true><<<dim3(L_ / 128, L_ / 128, H_), 256>>>(
        h, h + D_, S, DH_, W1N_, W1N_, L_,
        (long long)DH_, (long long)DH_, (long long)L_ * L_,
        0.08838834764831845f, nullptr, nullptr, nullptr);
    // 7. softmax rows
    softmax2048<<<H_ * L_, 256>>>(S);
    // 8. attn = P @ V
    gemm_tf32<2, false><<<dim3(1, L_ / 128, H_), 256>>>(
        S, h + 2 * D_, attn, L_, L_, W1N_, D_,
        (long long)L_ * L_, (long long)DH_, (long long)DH_,
        1.0f, nullptr, nullptr, nullptr);
    // 9. cat = [attn | gelu(mlp)]
    {
        size_t total = (size_t)L_ * CAT_;
        cat_kernel<<<(unsigned)((total + 255) / 256), 256>>>(attn, h, cat);
    }
    // 10. out = x + gate * (cat @ w2 + b2)
    gemm_tf32<3, false><<<dim3(D_ / 128, L_ / 128, 1), 256>>>(
        cat, w2, out, CAT_, CAT_, D_, D_, 0, 0, 0, 1.0f, b2, x, m + 2 * D_);
}

// round 9
// speedup vs baseline: 3.7485x; 1.3542x over previous
#include <cuda_runtime.h>
#include <cuda_bf16.h>
#include <math.h>
#include <stdint.h>

// ---------------------------------------------------------------------------
// SingleStreamBlock — tf32 mma.sync GEMMs with cp.async 4-stage pipeline
// (tcgen05 unavailable: harness compiles for .target sm_103, not sm_103a)
// Shapes: B=1, L=2048, D=3072, H=24, Dh=128, QKV=9216, MLP=12288, CAT=15360
// ---------------------------------------------------------------------------

#define L_   2048
#define D_   3072
#define H_   24
#define DH_  128
#define QKV_ 9216
#define W1N_ 21504      // QKV + 4*D
#define CAT_ 15360      // D + 4*D
#define EPS_ 1e-6f

// Scratch (device globals: allocation-free)
__device__ float g_sv[D_];
__device__ float g_m[3 * D_];
__device__ float g_xmod[(size_t)L_ * D_];
__device__ float g_h[(size_t)L_ * W1N_];
__device__ float g_S[(size_t)H_ * L_ * L_];
__device__ float g_attn[(size_t)L_ * D_];
__device__ float g_cat[(size_t)L_ * CAT_];

// ---------------------------------------------------------------------------
// small elementwise / reduction kernels
// ---------------------------------------------------------------------------
__global__ void silu_init(const float* __restrict__ v, const float* __restrict__ b,
                          float* __restrict__ sv, float* __restrict__ m) {
    int i = blockIdx.x * blockDim.x + threadIdx.x;
    if (i < D_) {
        float x = v[i];
        sv[i] = x / (1.0f + expf(-x));
    }
    if (i < 3 * D_) m[i] = b[i];
}

__global__ void mod_gemv(const float* __restrict__ sv, const float* __restrict__ w,
                         float* __restrict__ m) {
    __shared__ float s[384];
    int i0 = blockIdx.y * 384;
    for (int i = threadIdx.x; i < 384; i += 128) s[i] = sv[i0 + i];
    __syncthreads();
    int j = blockIdx.x * 128 + threadIdx.x;
    float acc = 0.f;
#pragma unroll 8
    for (int i = 0; i < 384; i++) acc += s[i] * w[(size_t)(i0 + i) * (3 * D_) + j];
    atomicAdd(&m[j], acc);
}

__global__ void ln_mod(const float* __restrict__ x, const float* __restrict__ m,
                       float* __restrict__ xmod) {
    __shared__ float r1[8], r2[8], bc[2];
    int row = blockIdx.x, t = threadIdx.x;
    const float* xr = x + (size_t)row * D_;
    float sum = 0.f, ss = 0.f;
    for (int i = t; i < D_; i += 256) {
        float v = xr[i];
        sum += v; ss += v * v;
    }
#pragma unroll
    for (int o = 16; o > 0; o >>= 1) {
        sum += __shfl_xor_sync(0xffffffffu, sum, o);
        ss  += __shfl_xor_sync(0xffffffffu, ss,  o);
    }
    if ((t & 31) == 0) { r1[t >> 5] = sum; r2[t >> 5] = ss; }
    __syncthreads();
    if (t == 0) {
        float a = 0.f, b = 0.f;
        for (int w = 0; w < 8; w++) { a += r1[w]; b += r2[w]; }
        bc[0] = a; bc[1] = b;
    }
    __syncthreads();
    float mu  = bc[0] * (1.0f / D_);
    float var = bc[1] * (1.0f / D_) - mu * mu;
    float inv = rsqrtf(var + EPS_);
    const float* shift = m;
    const float* scale = m + D_;
    float* orow = xmod + (size_t)row * D_;
    for (int i = t; i < D_; i += 256) {
        float v = (xr[i] - mu) * inv;
        orow[i] = (1.0f + scale[i]) * v + shift[i];
    }
}

__global__ void rmsrope(float* __restrict__ h, const float* __restrict__ pe,
                        const float* __restrict__ qs, const float* __restrict__ ks) {
    __shared__ float red[2];
    int l = blockIdx.x, hh = blockIdx.y, t = threadIdx.x;
    float* base = h + (size_t)l * W1N_ + hh * DH_;
    const float* p = pe + (size_t)l * 256 + t * 4;
    for (int s = 0; s < 2; s++) {
        float* ptr = base + s * D_;
        const float* g = s ? ks : qs;
        float a = ptr[2 * t], b = ptr[2 * t + 1];
        float sq = a * a + b * b;
#pragma unroll
        for (int o = 16; o > 0; o >>= 1) sq += __shfl_xor_sync(0xffffffffu, sq, o);
        if ((t & 31) == 0) red[t >> 5] = sq;
        __syncthreads();
        float tot = red[0] + red[1];
        float r = rsqrtf(tot * (1.0f / DH_) + EPS_);
        float na = a * r * g[2 * t];
        float nb = b * r * g[2 * t + 1];
        ptr[2 * t]     = p[0] * na + p[1] * nb;
        ptr[2 * t + 1] = p[2] * na + p[3] * nb;
        __syncthreads();
    }
}

__global__ void softmax2048(float* __restrict__ S) {
    __shared__ float r[8], bc;
    int t = threadIdx.x;
    float* row = S + (size_t)blockIdx.x * L_;
    float v[8];
    float mx = -1e30f;
#pragma unroll
    for (int i = 0; i < 8; i++) { v[i] = row[t + i * 256]; mx = fmaxf(mx, v[i]); }
#pragma unroll
    for (int o = 16; o > 0; o >>= 1) mx = fmaxf(mx, __shfl_xor_sync(0xffffffffu, mx, o));
    if ((t & 31) == 0) r[t >> 5] = mx;
    __syncthreads();
    if (t == 0) {
        float m2 = r[0];
        for (int w = 1; w < 8; w++) m2 = fmaxf(m2, r[w]);
        bc = m2;
    }
    __syncthreads();
    mx = bc;
    float sum = 0.f;
#pragma unroll
    for (int i = 0; i < 8; i++) { v[i] = expf(v[i] - mx); sum += v[i]; }
#pragma unroll
    for (int o = 16; o > 0; o >>= 1) sum += __shfl_xor_sync(0xffffffffu, sum, o);
    if ((t & 31) == 0) r[t >> 5] = sum;
    __syncthreads();
    if (t == 0) {
        float s2 = 0.f;
        for (int w = 0; w < 8; w++) s2 += r[w];
        bc = s2;
    }
    __syncthreads();
    float inv = 1.0f / bc;
#pragma unroll
    for (int i = 0; i < 8; i++) row[t + i * 256] = v[i] * inv;
}

__device__ __forceinline__ float gelu_tanh(float x) {
    float x3 = x * x * x;
    return 0.5f * x * (1.0f + tanhf(0.7978845608028654f * (x + 0.044715f * x3)));
}

__global__ void cat_kernel(const float* __restrict__ attn, const float* __restrict__ h,
                           float* __restrict__ cat) {
    size_t idx = (size_t)blockIdx.x * blockDim.x + threadIdx.x;
    if (idx >= (size_t)L_ * CAT_) return;
    int row = (int)(idx / CAT_);
    int c = (int)(idx % CAT_);
    float v;
    if (c < D_) v = attn[(size_t)row * D_ + c];
    else        v = gelu_tanh(h[(size_t)row * W1N_ + QKV_ + (c - D_)]);
    cat[idx] = v;
}

// ---------------------------------------------------------------------------
// tf32 mma.sync GEMM with cp.async 4-stage pipeline.
// BM=128, BK=16, BN in {128, 256}. 256 threads = 8 warps (2m x 4n).
// fp32 kept in smem (raw bits are valid tf32 operands: HW reads top 19 bits).
// A stored [m][k] stride 20 words  -> (20g+q)%32 bijective: conflict-free.
// B NN stored [k][n] stride BN+8   -> (8q+g)%32 bijective: conflict-free.
// B NT stored [n][k] stride 20     -> same pattern as A.
// Pipeline: commit every iteration (empty groups allowed), wait_group 2.
// EPI 0:+bias | 1:*alpha | 2:none | 3: xres + gate*(acc+bias)
// ---------------------------------------------------------------------------
#define CPA16(dst, src) \
    asm volatile("cp.async.cg.shared.global [%0], [%1], 16;" :: "r"(dst), "l"(src))
#define CP_COMMIT() asm volatile("cp.async.commit_group;" ::: "memory")
#define CP_WAIT2()  asm volatile("cp.async.wait_group 2;" ::: "memory")

__device__ __forceinline__ void mma_tf32(float c[4], const uint32_t a[4],
                                         const uint32_t b[2]) {
    asm volatile(
        "mma.sync.aligned.m16n8k8.row.col.f32.tf32.tf32.f32 "
        "{%0,%1,%2,%3}, {%4,%5,%6,%7}, {%8,%9}, {%0,%1,%2,%3};"
        : "+f"(c[0]), "+f"(c[1]), "+f"(c[2]), "+f"(c[3])
        : "r"(a[0]), "r"(a[1]), "r"(a[2]), "r"(a[3]), "r"(b[0]), "r"(b[1]));
}

template <int EPI, bool NT, int BN>
__global__ __launch_bounds__(256) void gemm_cp(
    const float* __restrict__ A, const float* __restrict__ B, float* __restrict__ C,
    int K, int lda, int ldb, int ldc,
    long long sA, long long sB, long long sC, float alpha,
    const float* __restrict__ bias, const float* __restrict__ xres,
    const float* __restrict__ gate)
{
    constexpr int AW = 128 * 20;                         // A stage words
    constexpr int BW = NT ? BN * 20 : 16 * (BN + 8);     // B stage words
    constexpr int STGW = AW + BW;
    constexpr int NJ = BN / 32;
    extern __shared__ float sm[];

    A += (long long)blockIdx.z * sA;
    B += (long long)blockIdx.z * sB;
    C += (long long)blockIdx.z * sC;
    const int m0 = blockIdx.x * 128, n0 = blockIdx.y * BN;
    const int tid = threadIdx.x;
    const int warp = tid >> 5, lane = tid & 31;
    const int wm = (warp & 1) * 64;
    const int wn = (warp >> 1) * (BN / 4);
    const int g = lane >> 2, q = lane & 3;

    const uint32_t sbase = (uint32_t)__cvta_generic_to_shared(sm);

    float acc[4][NJ][4];
#pragma unroll
    for (int mi = 0; mi < 4; mi++)
#pragma unroll
        for (int nj = 0; nj < NJ; nj++)
#pragma unroll
            for (int e = 0; e < 4; e++) acc[mi][nj][e] = 0.f;

    const int nk = K >> 4;

    auto issue = [&](int kt, int s) {
        const uint32_t as = sbase + (uint32_t)(s * STGW * 4);
        const uint32_t bs = as + AW * 4;
        const int k0 = kt << 4;
        // A tile: 128 rows x 16 k = 512 16B chunks (2 per thread)
#pragma unroll
        for (int i = 0; i < 2; i++) {
            int ch = tid + 256 * i;
            int r = ch >> 2, c = ch & 3;
            CPA16(as + (uint32_t)(r * 80 + c * 16),
                  A + (size_t)(m0 + r) * lda + k0 + c * 4);
        }
        if (NT) {   // B tile: BN rows x 16 k
#pragma unroll
            for (int i = 0; i < BN / 64; i++) {
                int ch = tid + 256 * i;
                int r = ch >> 2, c = ch & 3;
                CPA16(bs + (uint32_t)(r * 80 + c * 16),
                      B + (size_t)(n0 + r) * ldb + k0 + c * 4);
            }
        } else {    // B tile: 16 k x BN cols
#pragma unroll
            for (int i = 0; i < BN / 64; i++) {
                int ch = tid + 256 * i;
                int r = ch / (BN / 4), c = ch % (BN / 4);
                CPA16(bs + (uint32_t)(r * (BN + 8) * 4 + c * 16),
                      B + (size_t)(k0 + r) * ldb + n0 + c * 4);
            }
        }
    };

    // prologue: 3 committed groups (empty commits keep count uniform)
    for (int s = 0; s < 3; s++) {
        if (s < nk) issue(s, s);
        CP_COMMIT();
    }

    for (int it = 0; it < nk; it++) {
        CP_WAIT2();           // group 'it' complete
        __syncthreads();      // data visible; stage (it-1)&3 free for reuse
        if (it + 3 < nk) issue(it + 3, (it + 3) & 3);
        CP_COMMIT();

        const float* as = sm + (size_t)(it & 3) * STGW;
        const float* bs = as + AW;
#pragma unroll
        for (int ksp = 0; ksp < 2; ksp++) {
            const int kq = ksp * 8 + q;
            uint32_t af[4][4];
#pragma unroll
            for (int mi = 0; mi < 4; mi++) {
                const float* ap = as + (wm + mi * 16 + g) * 20 + kq;
                af[mi][0] = __float_as_uint(ap[0]);
                af[mi][1] = __float_as_uint(ap[160]);   // row +8
                af[mi][2] = __float_as_uint(ap[4]);     // k +4
                af[mi][3] = __float_as_uint(ap[164]);
            }
            uint32_t bf[NJ][2];
#pragma unroll
            for (int nj = 0; nj < NJ; nj++) {
                if (NT) {
                    const float* bp = bs + (wn + nj * 8 + g) * 20 + kq;
                    bf[nj][0] = __float_as_uint(bp[0]);
                    bf[nj][1] = __float_as_uint(bp[4]);
                } else {
                    const float* bp = bs + kq * (BN + 8) + wn + nj * 8 + g;
                    bf[nj][0] = __float_as_uint(bp[0]);
                    bf[nj][1] = __float_as_uint(bp[4 * (BN + 8)]);
                }
            }
#pragma unroll
            for (int mi = 0; mi < 4; mi++)
#pragma unroll
                for (int nj = 0; nj < NJ; nj++)
                    mma_tf32(acc[mi][nj], af[mi], bf[nj]);
        }
    }

    // epilogue: c0,c1 at (row g, col 2q); c2,c3 at (row g+8)
#pragma unroll
    for (int mi = 0; mi < 4; mi++) {
#pragma unroll
        for (int hh = 0; hh < 2; hh++) {
            size_t row = (size_t)(m0 + wm + mi * 16 + g + hh * 8);
#pragma unroll
            for (int nj = 0; nj < NJ; nj++) {
                int col = n0 + wn + nj * 8 + 2 * q;
                float v0 = acc[mi][nj][hh * 2 + 0];
                float v1 = acc[mi][nj][hh * 2 + 1];
                if (EPI == 0) {
                    v0 += bias[col]; v1 += bias[col + 1];
                } else if (EPI == 1) {
                    v0 *= alpha; v1 *= alpha;
                } else if (EPI == 3) {
                    v0 = xres[row * ldc + col]     + gate[col]     * (v0 + bias[col]);
                    v1 = xres[row * ldc + col + 1] + gate[col + 1] * (v1 + bias[col + 1]);
                }
                *(float2*)(C + row * ldc + col) = make_float2(v0, v1);
            }
        }
    }
}

// stage sizes in bytes (x4 stages)
#define SMEM_NN256 ((128 * 20 + 16 * 264) * 4 * 4)   // 108544
#define SMEM_NT256 ((128 * 20 + 256 * 20) * 4 * 4)   // 122880
#define SMEM_NN128 ((128 * 20 + 16 * 136) * 4 * 4)   // 75776

// ---------------------------------------------------------------------------
// launcher
// ---------------------------------------------------------------------------
extern "C" void kernel_launch(void* const* d_in, const int* in_sizes, int n_in,
                              void* d_out, int out_size) {
    const float* x      = (const float*)d_in[0];
    const float* vec    = (const float*)d_in[1];
    const float* pe     = (const float*)d_in[2];
    const float* w_mod  = (const float*)d_in[3];
    const float* b_mod  = (const float*)d_in[4];
    const float* w1     = (const float*)d_in[5];
    const float* b1     = (const float*)d_in[6];
    const float* w2     = (const float*)d_in[7];
    const float* b2     = (const float*)d_in[8];
    const float* qscale = (const float*)d_in[9];
    const float* kscale = (const float*)d_in[10];
    float* out = (float*)d_out;

    float *sv, *m, *xmod, *h, *S, *attn, *cat;
    cudaGetSymbolAddress((void**)&sv,   g_sv);
    cudaGetSymbolAddress((void**)&m,    g_m);
    cudaGetSymbolAddress((void**)&xmod, g_xmod);
    cudaGetSymbolAddress((void**)&h,    g_h);
    cudaGetSymbolAddress((void**)&S,    g_S);
    cudaGetSymbolAddress((void**)&attn, g_attn);
    cudaGetSymbolAddress((void**)&cat,  g_cat);

    cudaFuncSetAttribute(gemm_cp<0, false, 256>,
                         cudaFuncAttributeMaxDynamicSharedMemorySize, SMEM_NN256);
    cudaFuncSetAttribute(gemm_cp<1, true, 256>,
                         cudaFuncAttributeMaxDynamicSharedMemorySize, SMEM_NT256);
    cudaFuncSetAttribute(gemm_cp<2, false, 128>,
                         cudaFuncAttributeMaxDynamicSharedMemorySize, SMEM_NN128);
    cudaFuncSetAttribute(gemm_cp<3, false, 128>,
                         cudaFuncAttributeMaxDynamicSharedMemorySize, SMEM_NN128);

    // 1. sv = silu(vec); m = b_mod
    silu_init<<<(3 * D_) / 256, 256>>>(vec, b_mod, sv, m);
    // 2. m += sv @ w_mod
    mod_gemv<<<dim3(72, 8), 128>>>(sv, w_mod, m);
    // 3. layernorm + modulate
    ln_mod<<<L_, 256>>>(x, m, xmod);
    // 4. h = xmod @ w1 + b1   (m-tiles fast -> w1 tiles L2-reused across m)
    gemm_cp<0, false, 256><<<dim3(L_ / 128, W1N_ / 256), 256, SMEM_NN256>>>(
        xmod, w1, h, D_, D_, W1N_, W1N_, 0, 0, 0, 1.0f, b1, nullptr, nullptr);
    // 5. q/k rmsnorm + rope (in-place in h)
    rmsrope<<<dim3(L_, H_), 64>>>(h, pe, qscale, kscale);
    // 6. S = Q @ K^T * Dh^-0.5   (batched over heads, NT)
    gemm_cp<1, true, 256><<<dim3(L_ / 128, L_ / 256, H_), 256, SMEM_NT256>>>(
        h, h + D_, S, DH_, W1N_, W1N_, L_,
        (long long)DH_, (long long)DH_, (long long)L_ * L_,
        0.08838834764831845f, nullptr, nullptr, nullptr);
    // 7. softmax rows
    softmax2048<<<H_ * L_, 256>>>(S);
    // 8. attn = P @ V   (batched over heads, NN, N=128)
    gemm_cp<2, false, 128><<<dim3(L_ / 128, 1, H_), 256, SMEM_NN128>>>(
        S, h + 2 * D_, attn, L_, L_, W1N_, D_,
        (long long)L_ * L_, (long long)DH_, (long long)DH_,
        1.0f, nullptr, nullptr, nullptr);
    // 9. cat = [attn | gelu(mlp)]
    {
        size_t total = (size_t)L_ * CAT_;
        cat_kernel<<<(unsigned)((total + 255) / 256), 256>>>(attn, h, cat);
    }
    // 10. out = x + gate * (cat @ w2 + b2)   (BN=128: 384 CTAs, better tail)
    gemm_cp<3, false, 128><<<dim3(L_ / 128, D_ / 128), 256, SMEM_NN128>>>(
        cat, w2, out, CAT_, CAT_, D_, D_, 0, 0, 0, 1.0f, b2, x, m + 2 * D_);
}